// round 5
// baseline (speedup 1.0000x reference)
#include <cuda_runtime.h>

#define NSTEPS 50
#define LRATE  0.1f
#define BMAX   8192

__device__ float g_c0[BMAX];

typedef unsigned long long u64;

__device__ __forceinline__ u64 pk2(float lo, float hi) {
    u64 r; asm("mov.b64 %0, {%1,%2};" : "=l"(r) : "f"(lo), "f"(hi)); return r;
}
__device__ __forceinline__ void upk2(u64 v, float& lo, float& hi) {
    asm("mov.b64 {%0,%1}, %2;" : "=f"(lo), "=f"(hi) : "l"(v));
}
__device__ __forceinline__ void fma2(u64& d, u64 a, u64 b) {
    asm("fma.rn.f32x2 %0, %1, %2, %0;" : "+l"(d) : "l"(a), "l"(b));
}

// ---------------------------------------------------------------------------
// Kernel 1: 1-D nearest neighbor (|ci-cj| == sqrt((ci-cj)^2) exactly in RN).
// ---------------------------------------------------------------------------
#define NN_TILE 2048
__global__ __launch_bounds__(256) void nn_kernel(const float* __restrict__ c, int B) {
    __shared__ float ct[NN_TILE];
    int lane = threadIdx.x & 31;
    int w    = threadIdx.x >> 5;
    int q    = blockIdx.x * 8 + w;
    float cq = (q < B) ? c[q] : 0.f;
    float bestD = 3.0e38f; int bestJ = 0;
    for (int t0 = 0; t0 < B; t0 += NN_TILE) {
        int nt = min(NN_TILE, B - t0);
        __syncthreads();
        for (int i = threadIdx.x; i < nt; i += 256) ct[i] = c[t0 + i];
        __syncthreads();
        for (int jj = lane; jj < nt; jj += 32) {
            int j = t0 + jj;
            float d = fabsf(cq - ct[jj]);
            if (j == q) d += 1e9f;
            if (d < bestD) { bestD = d; bestJ = j; }
        }
    }
#pragma unroll
    for (int off = 16; off; off >>= 1) {
        float dO = __shfl_down_sync(0xffffffffu, bestD, off);
        int   jO = __shfl_down_sync(0xffffffffu, bestJ, off);
        if (dO < bestD || (dO == bestD && jO < bestJ)) { bestD = dO; bestJ = jO; }
    }
    if (lane == 0 && q < B) g_c0[q] = c[bestJ];
}

// ---------------------------------------------------------------------------
// 64-k tile matvec: thread owns 8 neurons (4 f32x2 pairs) x 2 samples.
// acc[2p+si]. Weights W[k][n] natural floats (row 64); acts A[k][32] dup u64.
// ---------------------------------------------------------------------------
__device__ __forceinline__ void mv(const float* __restrict__ W,
                                   const u64* __restrict__ A,
                                   int n0, int sG2, u64 acc[8]) {
#pragma unroll 16
    for (int k = 0; k < 64; k++) {
        ulonglong2 wA = *(const ulonglong2*)(W + k * 64 + n0);      // pairs 0,1
        ulonglong2 wB = *(const ulonglong2*)(W + k * 64 + n0 + 4);  // pairs 2,3
        ulonglong2 h  = *(const ulonglong2*)(A + k * 32 + sG2);     // dup s0,s1
        fma2(acc[0], wA.x, h.x); fma2(acc[1], wA.x, h.y);
        fma2(acc[2], wA.y, h.x); fma2(acc[3], wA.y, h.y);
        fma2(acc[4], wB.x, h.x); fma2(acc[5], wB.x, h.y);
        fma2(acc[6], wB.y, h.x); fma2(acc[7], wB.y, h.y);
    }
}

// acc -> v[r][si]
__device__ __forceinline__ void unpack(const u64 acc[8], float v[8][2]) {
#pragma unroll
    for (int p = 0; p < 4; p++)
#pragma unroll
        for (int si = 0; si < 2; si++)
            upk2(acc[p * 2 + si], v[2 * p][si], v[2 * p + 1][si]);
}

__device__ __forceinline__ void store_dup(u64* __restrict__ Y, int n0, int sG2,
                                          const float v[8][2]) {
#pragma unroll
    for (int r = 0; r < 8; r++) {
        ulonglong2 t;
        t.x = pk2(v[r][0], v[r][0]);
        t.y = pk2(v[r][1], v[r][1]);
        *(ulonglong2*)(Y + (n0 + r) * 32 + sG2) = t;
    }
}

// ---------------------------------------------------------------------------
// Kernel 2: block = 128 threads = 64 neurons x 32 samples; 2 blocks/SM.
// sG = tid&15 (16 sample-groups of 2), nG = tid>>4 (8 neuron-groups of 8).
// ---------------------------------------------------------------------------
__global__ __launch_bounds__(128, 2) void solver_kernel(
    const float* __restrict__ x,
    const float* __restrict__ W1, const float* __restrict__ b1,
    const float* __restrict__ W2, const float* __restrict__ b2,
    const float* __restrict__ W3, const float* __restrict__ b3,
    const float* __restrict__ W4,
    float* __restrict__ out)
{
    extern __shared__ __align__(16) char smraw[];
    float* W2T = (float*)smraw;                 // [64][64] W2T[k][n]=W2[n][k]
    float* W3T = W2T + 4096;
    float* W2N = W3T + 4096;                    // natural
    float* W3N = W2N + 4096;
    u64*  ActA = (u64*)(W3N + 4096);            // [64][32] dup
    u64*  ActB = ActA + 2048;
    u64*  b2d  = ActB + 2048;                   // [32] f32x2 bias pairs
    u64*  b3d  = b2d + 32;
    float* red = (float*)(b3d + 32);            // [4][32]

    int tid = threadIdx.x;
    int lane = tid & 31, warp = tid >> 5;
    int sG = tid & 15, nG = tid >> 4;
    int n0 = nG * 8, sG2 = sG * 2;

    for (int i = tid; i < 1024; i += 128) {
        ((float4*)W2N)[i] = ((const float4*)W2)[i];
        ((float4*)W3N)[i] = ((const float4*)W3)[i];
    }
    __syncthreads();
    for (int i = tid; i < 4096; i += 128) {
        int n = i >> 6, k = i & 63;
        W2T[k * 64 + n] = W2N[i];
        W3T[k * 64 + n] = W3N[i];
    }
    if (tid < 32) {
        b2d[tid] = pk2(b2[2 * tid], b2[2 * tid + 1]);
        b3d[tid] = pk2(b3[2 * tid], b3[2 * tid + 1]);
    }

    int gs = blockIdx.x * 32 + sG * 2;          // this thread's 2 samples
    float xs[2], cs[2];
#pragma unroll
    for (int si = 0; si < 2; si++) { xs[si] = x[gs + si]; cs[si] = g_c0[gs + si]; }

    float a[8][2], w1y[8], w4r[8];
#pragma unroll
    for (int r = 0; r < 8; r++) {
        int n = n0 + r;
        float w1x = W1[n * 3 + 0]; w1y[r] = W1[n * 3 + 1];
        float w1c = W1[n * 3 + 2]; float bb = b1[n];
        w4r[r] = W4[n];
#pragma unroll
        for (int si = 0; si < 2; si++)
            a[r][si] = fmaf(w1x, xs[si], fmaf(w1c, cs[si], bb));
    }
    __syncthreads();

    float y[2] = {0.f, 0.f};                    // Y_MEAN = 0

    for (int step = 0; step < NSTEPS; step++) {
        // ---- layer 1 (rank-1 in y) -> h1 ----
        unsigned m1 = 0;
        float v[8][2];
#pragma unroll
        for (int r = 0; r < 8; r++)
#pragma unroll
            for (int si = 0; si < 2; si++) {
                float z = fmaf(w1y[r], y[si], a[r][si]);
                if (z > 0.f) m1 |= 1u << (r * 2 + si);
                v[r][si] = fmaxf(z, 0.f);
            }
        store_dup(ActA, n0, sG2, v);
        __syncthreads();

        // ---- fwd2: z2 = W2 h1 + b2 ----
        u64 acc[8];
        {
            ulonglong2 ba = *(const ulonglong2*)(b2d + nG * 4);
            ulonglong2 bb = *(const ulonglong2*)(b2d + nG * 4 + 2);
            acc[0] = ba.x; acc[1] = ba.x; acc[2] = ba.y; acc[3] = ba.y;
            acc[4] = bb.x; acc[5] = bb.x; acc[6] = bb.y; acc[7] = bb.y;
        }
        mv(W2T, ActA, n0, sG2, acc);
        unsigned m2 = 0;
        unpack(acc, v);
#pragma unroll
        for (int r = 0; r < 8; r++)
#pragma unroll
            for (int si = 0; si < 2; si++) {
                if (v[r][si] > 0.f) m2 |= 1u << (r * 2 + si);
                v[r][si] = fmaxf(v[r][si], 0.f);
            }
        store_dup(ActB, n0, sG2, v);
        __syncthreads();

        // ---- fwd3: z3 = W3 h2 + b3 -> g3 = (z3>0)*W4 ----
        {
            ulonglong2 ba = *(const ulonglong2*)(b3d + nG * 4);
            ulonglong2 bb = *(const ulonglong2*)(b3d + nG * 4 + 2);
            acc[0] = ba.x; acc[1] = ba.x; acc[2] = ba.y; acc[3] = ba.y;
            acc[4] = bb.x; acc[5] = bb.x; acc[6] = bb.y; acc[7] = bb.y;
        }
        mv(W3T, ActB, n0, sG2, acc);
        unpack(acc, v);
#pragma unroll
        for (int r = 0; r < 8; r++)
#pragma unroll
            for (int si = 0; si < 2; si++)
                v[r][si] = (v[r][si] > 0.f) ? w4r[r] : 0.f;
        store_dup(ActA, n0, sG2, v);
        __syncthreads();

        // ---- bwd3: g2 = m2 .* (W3^T g3) ----
#pragma unroll
        for (int q = 0; q < 8; q++) acc[q] = 0;
        mv(W3N, ActA, n0, sG2, acc);
        unpack(acc, v);
#pragma unroll
        for (int r = 0; r < 8; r++)
#pragma unroll
            for (int si = 0; si < 2; si++)
                v[r][si] = (m2 & (1u << (r * 2 + si))) ? v[r][si] : 0.f;
        store_dup(ActB, n0, sG2, v);
        __syncthreads();

        // ---- bwd2: g1 = m1 .* (W2^T g2); gy = sum_n w1y[n] g1[n] ----
#pragma unroll
        for (int q = 0; q < 8; q++) acc[q] = 0;
        mv(W2N, ActB, n0, sG2, acc);
        unpack(acc, v);
        float pg[2] = {0.f, 0.f};
#pragma unroll
        for (int r = 0; r < 8; r++)
#pragma unroll
            for (int si = 0; si < 2; si++) {
                float g = (m1 & (1u << (r * 2 + si))) ? v[r][si] : 0.f;
                pg[si] = fmaf(w1y[r], g, pg[si]);
            }
        // combine the warp's two neuron-groups (lanes differ in bit 4)
#pragma unroll
        for (int si = 0; si < 2; si++)
            pg[si] += __shfl_xor_sync(0xffffffffu, pg[si], 16);
        if (!(lane & 16)) {
            float2 t = make_float2(pg[0], pg[1]);
            *(float2*)(red + warp * 32 + sG * 2) = t;
        }
        __syncthreads();
        {
            float2 r0 = *(const float2*)(red + 0 * 32 + sG * 2);
            float2 r1 = *(const float2*)(red + 1 * 32 + sG * 2);
            float2 r2 = *(const float2*)(red + 2 * 32 + sG * 2);
            float2 r3 = *(const float2*)(red + 3 * 32 + sG * 2);
            y[0] -= LRATE * ((r0.x + r1.x) + (r2.x + r3.x));
            y[1] -= LRATE * ((r0.y + r1.y) + (r2.y + r3.y));
        }
    }

    if (nG == 0) {
        float2 t = make_float2(y[0], y[1]);
        *(float2*)(out + gs) = t;
    }
}

// ---------------------------------------------------------------------------
// Launch
// ---------------------------------------------------------------------------
extern "C" void kernel_launch(void* const* d_in, const int* in_sizes, int n_in,
                              void* d_out, int out_size) {
    const float* x  = (const float*)d_in[0];
    const float* c  = (const float*)d_in[1];
    const float* W1 = (const float*)d_in[2];
    const float* b1 = (const float*)d_in[3];
    const float* W2 = (const float*)d_in[4];
    const float* b2 = (const float*)d_in[5];
    const float* W3 = (const float*)d_in[6];
    const float* b3 = (const float*)d_in[7];
    const float* W4 = (const float*)d_in[8];
    // d_in[9] = b4: constant offset, no effect on dE/dy
    float* out = (float*)d_out;
    int B = in_sizes[0];

    // smem: 4*4096*4 (weights) + 2*2048*8 (acts) + 64*8 (bias) + 128*4 (red)
    const int SMEM = 4 * 4096 * 4 + 2 * 2048 * 8 + 64 * 8 + 128 * 4; // 99328 B
    cudaFuncSetAttribute(solver_kernel,
                         cudaFuncAttributeMaxDynamicSharedMemorySize, SMEM);

    nn_kernel<<<(B + 7) / 8, 256>>>(c, B);
    solver_kernel<<<B / 32, 128, SMEM>>>(x, W1, b1, W2, b2, W3, b3, W4, out);
}